// round 11
// baseline (speedup 1.0000x reference)
#include <cuda_runtime.h>
#include <cuda_fp16.h>

#define NN 50000
#define EE 800000
#define DD 64
#define SCAN_BLOCKS 49   // ceil(NN / 1024)

// ---------------- scratch (static device globals; no allocation) ----------------
__device__ __align__(16) int    g_csr_src[EE];     // src ids grouped by dst
__device__ __align__(16) __half g_hxh[NN * DD];    // fp16 feature matrix (gather source)
__device__ __align__(16) float  g_ssrc[NN];
__device__ __align__(16) float  g_sdst[NN];
__device__ __align__(16) int    g_deg[NN];         // zero at entry; re-zeroed by k_scan
__device__ __align__(16) int    g_rowptr[NN + 4];
__device__ __align__(16) int    g_cursor[NN];
__device__ __align__(16) int    g_scansums[64];
__device__ __align__(16) int    g_scanflag[64];    // zero at entry; reset by last block
__device__ int g_scandone;                          // zero at entry; reset by last block

// ---------------- helpers ----------------

__device__ __forceinline__ int clampN(int v) { return min(max(v, 0), NN - 1); }

// per-block int64-vs-int32 layout detection: int64 indices (< 2^31) have zero
// high words at odd int32 positions.
__device__ __forceinline__ int block_is64(const int* __restrict__ ei) {
    __shared__ int s_is64;
    if (threadIdx.x < 32) {
        int nz = ei[2 * threadIdx.x + 1] | ei[2 * (threadIdx.x + 32) + 1];
        unsigned m = __ballot_sync(0xffffffffu, nz != 0);
        if (threadIdx.x == 0) s_is64 = (m == 0);
    }
    __syncthreads();
    return s_is64;
}

// load 4 consecutive int64 values' low words starting at element index e (e % 4 == 0)
__device__ __forceinline__ int4 load4_i64lo(const int* __restrict__ ei, int e) {
    const int4 a = *(const int4*)(ei + 2 * e);
    const int4 b = *(const int4*)(ei + 2 * e + 4);
    return make_int4(a.x, a.z, b.x, b.z);
}

// ---------------- CSR build ----------------

// histogram of dst; 4 edges per thread
__global__ void __launch_bounds__(256) k_hist(const int* __restrict__ ei) {
    const int is64 = block_is64(ei);
    const int e0 = (blockIdx.x * blockDim.x + threadIdx.x) * 4;
    if (e0 >= EE) return;
    int4 d4 = is64 ? load4_i64lo(ei, EE + e0) : *(const int4*)(ei + EE + e0);
    atomicAdd(&g_deg[clampN(d4.x)], 1);
    atomicAdd(&g_deg[clampN(d4.y)], 1);
    atomicAdd(&g_deg[clampN(d4.z)], 1);
    atomicAdd(&g_deg[clampN(d4.w)], 1);
}

// fused exclusive scan (decoupled lookback, 49 resident blocks) -> rowptr/cursor
// also re-zeroes g_deg and self-resets flags for graph replay.
__global__ void __launch_bounds__(256) k_scan() {
    const int tid = threadIdx.x;
    const int lane = tid & 31, warp = tid >> 5;
    const int base = blockIdx.x * 1024 + tid * 4;

    // load chunk of degrees; re-zero for next launch
    int4 v = make_int4(0, 0, 0, 0);
    if (base + 3 < NN) {
        v = *(const int4*)(g_deg + base);
        *(int4*)(g_deg + base) = make_int4(0, 0, 0, 0);
    } else {
        if (base + 0 < NN) { v.x = g_deg[base + 0]; g_deg[base + 0] = 0; }
        if (base + 1 < NN) { v.y = g_deg[base + 1]; g_deg[base + 1] = 0; }
        if (base + 2 < NN) { v.z = g_deg[base + 2]; g_deg[base + 2] = 0; }
        if (base + 3 < NN) { v.w = g_deg[base + 3]; g_deg[base + 3] = 0; }
    }
    const int s0 = v.x, s1 = s0 + v.y, s2 = s1 + v.z, s3 = s2 + v.w;
    const int tot = s3;

    // warp inclusive scan of per-thread totals
    int inc = tot;
    #pragma unroll
    for (int d = 1; d < 32; d <<= 1) {
        int a = __shfl_up_sync(0xffffffffu, inc, d);
        if (lane >= d) inc += a;
    }
    __shared__ int wtot[8];
    if (lane == 31) wtot[warp] = inc;
    __syncthreads();

    // block total -> publish for lookback
    if (tid == 0) {
        int bt = 0;
        #pragma unroll
        for (int i = 0; i < 8; i++) bt += wtot[i];
        g_scansums[blockIdx.x] = bt;
        __threadfence();
        atomicExch(&g_scanflag[blockIdx.x], 1);
    }

    // lookback: warp 0 sums predecessor block totals
    __shared__ int s_boff;
    if (warp == 0) {
        int acc = 0;
        for (int i = lane; i < blockIdx.x; i += 32) {
            while (atomicAdd(&g_scanflag[i], 0) == 0) { }
            acc += g_scansums[i];
        }
        __threadfence();
        #pragma unroll
        for (int o = 16; o > 0; o >>= 1) acc += __shfl_xor_sync(0xffffffffu, acc, o);
        if (lane == 0) s_boff = acc;
    }
    __syncthreads();

    int woff = 0;
    for (int i = 0; i < warp; i++) woff += wtot[i];

    const int off = s_boff + woff + (inc - tot);
    const int4 rp = make_int4(off, off + s0, off + s1, off + s2);
    if (base + 3 < NN) {
        *(int4*)(g_rowptr + base) = rp;
        *(int4*)(g_cursor + base) = rp;
    } else {
        if (base + 0 < NN) { g_rowptr[base + 0] = rp.x; g_cursor[base + 0] = rp.x; }
        if (base + 1 < NN) { g_rowptr[base + 1] = rp.y; g_cursor[base + 1] = rp.y; }
        if (base + 2 < NN) { g_rowptr[base + 2] = rp.z; g_cursor[base + 2] = rp.z; }
        if (base + 3 < NN) { g_rowptr[base + 3] = rp.w; g_cursor[base + 3] = rp.w; }
    }
    if (blockIdx.x == 0 && tid == 0) g_rowptr[NN] = EE;

    // last finishing block resets flags/done so graph replay starts clean
    __syncthreads();
    if (tid == 0) {
        const int n = atomicAdd(&g_scandone, 1);
        if (n == gridDim.x - 1) {
            for (int i = 0; i < 64; i++) g_scanflag[i] = 0;
            g_scandone = 0;
            __threadfence();
        }
    }
}

// fill CSR; 4 edges per thread
__global__ void __launch_bounds__(256) k_fill(const int* __restrict__ ei) {
    const int is64 = block_is64(ei);
    const int e0 = (blockIdx.x * blockDim.x + threadIdx.x) * 4;
    if (e0 >= EE) return;
    int4 s4, d4;
    if (is64) {
        s4 = load4_i64lo(ei, e0);
        d4 = load4_i64lo(ei, EE + e0);
    } else {
        s4 = *(const int4*)(ei + e0);
        d4 = *(const int4*)(ei + EE + e0);
    }
    int p0 = atomicAdd(&g_cursor[clampN(d4.x)], 1);
    int p1 = atomicAdd(&g_cursor[clampN(d4.y)], 1);
    int p2 = atomicAdd(&g_cursor[clampN(d4.z)], 1);
    int p3 = atomicAdd(&g_cursor[clampN(d4.w)], 1);
    g_csr_src[p0] = clampN(s4.x);
    g_csr_src[p1] = clampN(s4.y);
    g_csr_src[p2] = clampN(s4.z);
    g_csr_src[p3] = clampN(s4.w);
}

// ---------------- tensor-core GEMM: 128-row tile, 8 warps, m16n8k16 ----------------
__global__ void __launch_bounds__(256) k_gemm_tc(
        const float* __restrict__ h, const float* __restrict__ W,
        const float* __restrict__ bias, int do_relu,
        const float* __restrict__ a_s, const float* __restrict__ a_d,
        float* __restrict__ out) {
    __shared__ __half sA[128 * 72];    // A tile fp16, pitch 72
    __shared__ __half sWt[64 * 72];    // W transposed: sWt[n][k]

    const int tid = threadIdx.x;
    const int warp = tid >> 5, lane = tid & 31;
    const int g = lane >> 2, tg = lane & 3;
    const int r0blk = blockIdx.x * 128;

    for (int idx = tid; idx < 4096; idx += 256) {
        const int k = idx >> 6, n = idx & 63;
        sWt[n * 72 + k] = __float2half_rn(W[idx]);
    }
    {
        const int row = tid >> 1;
        const int c0 = (tid & 1) * 32;
        const int r = r0blk + row;
        if (r < NN) {
            const float4* src = (const float4*)(h + r * 64 + c0);
            #pragma unroll
            for (int i = 0; i < 8; i++) {
                const float4 v = src[i];
                *(__half2*)(sA + row * 72 + c0 + i * 4)     = __floats2half2_rn(v.x, v.y);
                *(__half2*)(sA + row * 72 + c0 + i * 4 + 2) = __floats2half2_rn(v.z, v.w);
            }
        } else {
            const __half2 z = __half2half2(__float2half(0.f));
            #pragma unroll
            for (int i = 0; i < 16; i++)
                *(__half2*)(sA + row * 72 + c0 + i * 2) = z;
        }
    }
    __syncthreads();

    const int rw = warp * 16;
    float acc[8][4];
    #pragma unroll
    for (int i = 0; i < 8; i++)
        #pragma unroll
        for (int j = 0; j < 4; j++) acc[i][j] = 0.f;

    #pragma unroll
    for (int k0 = 0; k0 < 64; k0 += 16) {
        const unsigned a0 = *(const unsigned*)(sA + (rw + g)     * 72 + k0 + 2 * tg);
        const unsigned a1 = *(const unsigned*)(sA + (rw + g + 8) * 72 + k0 + 2 * tg);
        const unsigned a2 = *(const unsigned*)(sA + (rw + g)     * 72 + k0 + 8 + 2 * tg);
        const unsigned a3 = *(const unsigned*)(sA + (rw + g + 8) * 72 + k0 + 8 + 2 * tg);
        #pragma unroll
        for (int i = 0; i < 8; i++) {
            const int n0 = i * 8;
            const unsigned b0 = *(const unsigned*)(sWt + (n0 + g) * 72 + k0 + 2 * tg);
            const unsigned b1 = *(const unsigned*)(sWt + (n0 + g) * 72 + k0 + 8 + 2 * tg);
            asm volatile(
                "mma.sync.aligned.m16n8k16.row.col.f32.f16.f16.f32 "
                "{%0,%1,%2,%3}, {%4,%5,%6,%7}, {%8,%9}, {%0,%1,%2,%3};"
                : "+f"(acc[i][0]), "+f"(acc[i][1]), "+f"(acc[i][2]), "+f"(acc[i][3])
                : "r"(a0), "r"(a1), "r"(a2), "r"(a3), "r"(b0), "r"(b1));
        }
    }

    const int rA = r0blk + rw + g;
    const int rB = rA + 8;
    float vsA = 0.f, vdA = 0.f, vsB = 0.f, vdB = 0.f;

    #pragma unroll
    for (int i = 0; i < 8; i++) {
        const int c = i * 8 + 2 * tg;
        float bx = 0.f, by = 0.f;
        if (bias) { bx = bias[c]; by = bias[c + 1]; }
        float v0 = acc[i][0] + bx, v1 = acc[i][1] + by;
        float v2 = acc[i][2] + bx, v3 = acc[i][3] + by;
        if (do_relu) {
            v0 = fmaxf(v0, 0.f); v1 = fmaxf(v1, 0.f);
            v2 = fmaxf(v2, 0.f); v3 = fmaxf(v3, 0.f);
        }
        if (out) {
            if (rA < NN) { float2 p = make_float2(v0, v1); *(float2*)(out + rA * 64 + c) = p; }
            if (rB < NN) { float2 p = make_float2(v2, v3); *(float2*)(out + rB * 64 + c) = p; }
        } else {
            if (rA < NN) *(__half2*)(g_hxh + rA * 64 + c) = __floats2half2_rn(v0, v1);
            if (rB < NN) *(__half2*)(g_hxh + rB * 64 + c) = __floats2half2_rn(v2, v3);
        }
        if (a_s) {
            const float as0 = a_s[c], as1 = a_s[c + 1];
            const float ad0 = a_d[c], ad1 = a_d[c + 1];
            vsA += v0 * as0 + v1 * as1; vdA += v0 * ad0 + v1 * ad1;
            vsB += v2 * as0 + v3 * as1; vdB += v2 * ad0 + v3 * ad1;
        }
    }
    if (a_s) {
        #pragma unroll
        for (int o = 2; o > 0; o >>= 1) {
            vsA += __shfl_down_sync(0xffffffffu, vsA, o, 4);
            vdA += __shfl_down_sync(0xffffffffu, vdA, o, 4);
            vsB += __shfl_down_sync(0xffffffffu, vsB, o, 4);
            vdB += __shfl_down_sync(0xffffffffu, vdB, o, 4);
        }
        if (tg == 0) {
            if (rA < NN) { g_ssrc[rA] = vsA; g_sdst[rA] = vdA; }
            if (rB < NN) { g_ssrc[rB] = vsB; g_sdst[rB] = vdB; }
        }
    }
}

// ---------------- fused GAT aggregate: one warp per dst node ----------------
__global__ void __launch_bounds__(256) k_gat(float* __restrict__ out,
                                             const float* __restrict__ bias) {
    const int warp = threadIdx.x >> 5;
    const int lane = threadIdx.x & 31;
    const int node = blockIdx.x * 8 + warp;
    if (node >= NN) return;

    const int base = g_rowptr[node];
    const int end  = g_rowptr[node + 1];
    const float sdi = g_sdst[node];

    const int quarter = lane >> 3;
    const int sub     = lane & 7;
    float f[8];
    #pragma unroll
    for (int i = 0; i < 8; i++) f[i] = 0.f;
    float esum = 0.f;

    #pragma unroll 2
    for (int j = base + quarter; j < end; j += 4) {
        const int s = g_csr_src[j];
        float a = g_ssrc[s] + sdi;
        a = (a >= 0.f) ? a : 0.2f * a;
        const float e = __expf(a);
        const uint4 raw = *(const uint4*)(g_hxh + s * 64 + sub * 8);
        const __half2* hp = (const __half2*)&raw;
        const float2 f0 = __half22float2(hp[0]);
        const float2 f1 = __half22float2(hp[1]);
        const float2 f2 = __half22float2(hp[2]);
        const float2 f3 = __half22float2(hp[3]);
        f[0] = fmaf(e, f0.x, f[0]); f[1] = fmaf(e, f0.y, f[1]);
        f[2] = fmaf(e, f1.x, f[2]); f[3] = fmaf(e, f1.y, f[3]);
        f[4] = fmaf(e, f2.x, f[4]); f[5] = fmaf(e, f2.y, f[5]);
        f[6] = fmaf(e, f3.x, f[6]); f[7] = fmaf(e, f3.y, f[7]);
        esum += e;
    }
    #pragma unroll
    for (int o = 8; o <= 16; o <<= 1) {
        esum += __shfl_xor_sync(0xffffffffu, esum, o);
        #pragma unroll
        for (int i = 0; i < 8; i++)
            f[i] += __shfl_xor_sync(0xffffffffu, f[i], o);
    }

    const float inv = (end > base) ? (1.0f / esum) : 0.0f;

    if (quarter == 0) {
        float4 ob0 = *(float4*)(out + node * 64 + sub * 8);
        float4 ob1 = *(float4*)(out + node * 64 + sub * 8 + 4);
        const float4 bb0 = *(const float4*)(bias + sub * 8);
        const float4 bb1 = *(const float4*)(bias + sub * 8 + 4);
        ob0.x += fmaxf(fmaf(f[0], inv, bb0.x), 0.f);
        ob0.y += fmaxf(fmaf(f[1], inv, bb0.y), 0.f);
        ob0.z += fmaxf(fmaf(f[2], inv, bb0.z), 0.f);
        ob0.w += fmaxf(fmaf(f[3], inv, bb0.w), 0.f);
        ob1.x += fmaxf(fmaf(f[4], inv, bb1.x), 0.f);
        ob1.y += fmaxf(fmaf(f[5], inv, bb1.y), 0.f);
        ob1.z += fmaxf(fmaf(f[6], inv, bb1.z), 0.f);
        ob1.w += fmaxf(fmaf(f[7], inv, bb1.w), 0.f);
        *(float4*)(out + node * 64 + sub * 8)     = ob0;
        *(float4*)(out + node * 64 + sub * 8 + 4) = ob1;
    }
}

// ---------------- launch ----------------
extern "C" void kernel_launch(void* const* d_in, const int* in_sizes, int n_in,
                              void* d_out, int out_size) {
    const float* x   = (const float*)d_in[0];
    const int*   ei  = (const int*)d_in[1];
    const float* W0  = (const float*)d_in[4];
    const float* b0  = (const float*)d_in[5];
    const float* W1  = (const float*)d_in[6];
    const float* as1 = (const float*)d_in[7];
    const float* ad1 = (const float*)d_in[8];
    const float* b1  = (const float*)d_in[9];
    const float* W2  = (const float*)d_in[10];
    const float* as2 = (const float*)d_in[11];
    const float* ad2 = (const float*)d_in[12];
    const float* b2  = (const float*)d_in[13];
    float* out = (float*)d_out;

    const int edge4Blocks = (EE / 4 + 255) / 256;   // 4 edges per thread
    const int gemmBlocks  = (NN + 127) / 128;
    const int gatBlocks   = (NN + 7) / 8;

    k_hist<<<edge4Blocks, 256>>>(ei);
    k_scan<<<SCAN_BLOCKS, 256>>>();
    k_fill<<<edge4Blocks, 256>>>(ei);

    // layer 0: out = relu(x @ W0 + b0)
    k_gemm_tc<<<gemmBlocks, 256>>>(x, W0, b0, 1, nullptr, nullptr, out);

    // GAT layer 1
    k_gemm_tc<<<gemmBlocks, 256>>>(out, W1, nullptr, 0, as1, ad1, nullptr);
    k_gat<<<gatBlocks, 256>>>(out, b1);

    // GAT layer 2
    k_gemm_tc<<<gemmBlocks, 256>>>(out, W2, nullptr, 0, as2, ad2, nullptr);
    k_gat<<<gatBlocks, 256>>>(out, b2);
}

// round 13
// speedup vs baseline: 1.1344x; 1.1344x over previous
#include <cuda_runtime.h>
#include <cuda_fp16.h>

#define NN 50000
#define EE 800000
#define DD 64
#define SCAN_BLOCKS 49   // ceil(NN / 1024)

// ---------------- scratch (static device globals; no allocation) ----------------
__device__ __align__(16) int    g_csr_src[EE];     // src ids grouped by dst
__device__ __align__(16) __half g_hxh[NN * DD];    // fp16 feature matrix (gather source)
__device__ __align__(16) float  g_ssrc[NN];
__device__ __align__(16) float  g_sdst[NN];
__device__ __align__(16) int    g_deg[NN];         // zero at entry; re-zeroed by k_scanout
__device__ __align__(16) int    g_rowptr[NN + 4];
__device__ __align__(16) int    g_cursor[NN];
__device__ __align__(16) int    g_bsum[64];

// ---------------- helpers ----------------

__device__ __forceinline__ int clampN(int v) { return min(max(v, 0), NN - 1); }

// per-block int64-vs-int32 layout detection
__device__ __forceinline__ int block_is64(const int* __restrict__ ei) {
    __shared__ int s_is64;
    if (threadIdx.x < 32) {
        int nz = ei[2 * threadIdx.x + 1] | ei[2 * (threadIdx.x + 32) + 1];
        unsigned m = __ballot_sync(0xffffffffu, nz != 0);
        if (threadIdx.x == 0) s_is64 = (m == 0);
    }
    __syncthreads();
    return s_is64;
}

__device__ __forceinline__ int4 load4_i64lo(const int* __restrict__ ei, int e) {
    const int4 a = *(const int4*)(ei + 2 * e);
    const int4 b = *(const int4*)(ei + 2 * e + 4);
    return make_int4(a.x, a.z, b.x, b.z);
}

// ---------------- CSR build ----------------

// histogram of dst; 4 edges per thread
__global__ void __launch_bounds__(256) k_hist(const int* __restrict__ ei) {
    const int is64 = block_is64(ei);
    const int e0 = (blockIdx.x * blockDim.x + threadIdx.x) * 4;
    if (e0 >= EE) return;
    int4 d4 = is64 ? load4_i64lo(ei, EE + e0) : *(const int4*)(ei + EE + e0);
    atomicAdd(&g_deg[clampN(d4.x)], 1);
    atomicAdd(&g_deg[clampN(d4.y)], 1);
    atomicAdd(&g_deg[clampN(d4.z)], 1);
    atomicAdd(&g_deg[clampN(d4.w)], 1);
}

// scan pass 1: per-1024-chunk sums
__global__ void __launch_bounds__(256) k_scansum() {
    const int tid = threadIdx.x;
    const int lane = tid & 31, warp = tid >> 5;
    const int base = blockIdx.x * 1024 + tid * 4;
    int s = 0;
    if (base + 3 < NN) {
        const int4 v = *(const int4*)(g_deg + base);
        s = v.x + v.y + v.z + v.w;
    } else {
        #pragma unroll
        for (int i = 0; i < 4; i++) if (base + i < NN) s += g_deg[base + i];
    }
    #pragma unroll
    for (int o = 16; o > 0; o >>= 1) s += __shfl_xor_sync(0xffffffffu, s, o);
    __shared__ int ws[8];
    if (lane == 0) ws[warp] = s;
    __syncthreads();
    if (tid == 0) {
        int t = 0;
        #pragma unroll
        for (int i = 0; i < 8; i++) t += ws[i];
        g_bsum[blockIdx.x] = t;
    }
}

// scan pass 2: block offset from g_bsum, chunk scan -> rowptr/cursor; re-zero g_deg
__global__ void __launch_bounds__(256) k_scanout() {
    const int tid = threadIdx.x;
    const int lane = tid & 31, warp = tid >> 5;
    const int base = blockIdx.x * 1024 + tid * 4;

    __shared__ int s_boff;
    if (warp == 0) {
        int v = 0;
        if (lane < blockIdx.x) v = g_bsum[lane];
        if (lane + 32 < blockIdx.x) v += g_bsum[lane + 32];
        #pragma unroll
        for (int o = 16; o > 0; o >>= 1) v += __shfl_xor_sync(0xffffffffu, v, o);
        if (lane == 0) s_boff = v;
    }

    int4 v = make_int4(0, 0, 0, 0);
    if (base + 3 < NN) {
        v = *(const int4*)(g_deg + base);
        *(int4*)(g_deg + base) = make_int4(0, 0, 0, 0);
    } else {
        if (base + 0 < NN) { v.x = g_deg[base + 0]; g_deg[base + 0] = 0; }
        if (base + 1 < NN) { v.y = g_deg[base + 1]; g_deg[base + 1] = 0; }
        if (base + 2 < NN) { v.z = g_deg[base + 2]; g_deg[base + 2] = 0; }
        if (base + 3 < NN) { v.w = g_deg[base + 3]; g_deg[base + 3] = 0; }
    }
    const int s0 = v.x, s1 = s0 + v.y, s2 = s1 + v.z, s3 = s2 + v.w;
    const int tot = s3;

    int inc = tot;
    #pragma unroll
    for (int d = 1; d < 32; d <<= 1) {
        int a = __shfl_up_sync(0xffffffffu, inc, d);
        if (lane >= d) inc += a;
    }
    __shared__ int wtot[8];
    if (lane == 31) wtot[warp] = inc;
    __syncthreads();
    int woff = 0;
    for (int i = 0; i < warp; i++) woff += wtot[i];

    const int off = s_boff + woff + (inc - tot);
    const int4 rp = make_int4(off, off + s0, off + s1, off + s2);
    if (base + 3 < NN) {
        *(int4*)(g_rowptr + base) = rp;
        *(int4*)(g_cursor + base) = rp;
    } else {
        if (base + 0 < NN) { g_rowptr[base + 0] = rp.x; g_cursor[base + 0] = rp.x; }
        if (base + 1 < NN) { g_rowptr[base + 1] = rp.y; g_cursor[base + 1] = rp.y; }
        if (base + 2 < NN) { g_rowptr[base + 2] = rp.z; g_cursor[base + 2] = rp.z; }
        if (base + 3 < NN) { g_rowptr[base + 3] = rp.w; g_cursor[base + 3] = rp.w; }
    }
    if (blockIdx.x == 0 && tid == 0) g_rowptr[NN] = EE;
}

// fill CSR; 4 edges per thread
__global__ void __launch_bounds__(256) k_fill(const int* __restrict__ ei) {
    const int is64 = block_is64(ei);
    const int e0 = (blockIdx.x * blockDim.x + threadIdx.x) * 4;
    if (e0 >= EE) return;
    int4 s4, d4;
    if (is64) {
        s4 = load4_i64lo(ei, e0);
        d4 = load4_i64lo(ei, EE + e0);
    } else {
        s4 = *(const int4*)(ei + e0);
        d4 = *(const int4*)(ei + EE + e0);
    }
    int p0 = atomicAdd(&g_cursor[clampN(d4.x)], 1);
    int p1 = atomicAdd(&g_cursor[clampN(d4.y)], 1);
    int p2 = atomicAdd(&g_cursor[clampN(d4.z)], 1);
    int p3 = atomicAdd(&g_cursor[clampN(d4.w)], 1);
    g_csr_src[p0] = clampN(s4.x);
    g_csr_src[p1] = clampN(s4.y);
    g_csr_src[p2] = clampN(s4.z);
    g_csr_src[p3] = clampN(s4.w);
}

// ---------------- MMA helper ----------------
__device__ __forceinline__ void mma16n8k16(float acc[4], unsigned a0, unsigned a1,
                                           unsigned a2, unsigned a3,
                                           unsigned b0, unsigned b1) {
    asm volatile(
        "mma.sync.aligned.m16n8k16.row.col.f32.f16.f16.f32 "
        "{%0,%1,%2,%3}, {%4,%5,%6,%7}, {%8,%9}, {%0,%1,%2,%3};"
        : "+f"(acc[0]), "+f"(acc[1]), "+f"(acc[2]), "+f"(acc[3])
        : "r"(a0), "r"(a1), "r"(a2), "r"(a3), "r"(b0), "r"(b1));
}

// ---------------- fused layer0+layer1 GEMM ----------------
// out = relu(x @ W0 + b0)          (fp32 -> out)
// hx  = out @ W1                   (fp16 -> g_hxh; dots -> g_ssrc/g_sdst)
__global__ void __launch_bounds__(256) k_gemm2x(
        const float* __restrict__ x, const float* __restrict__ W0,
        const float* __restrict__ b0, const float* __restrict__ W1,
        const float* __restrict__ a_s, const float* __restrict__ a_d,
        float* __restrict__ out) {
    __shared__ __half sA[128 * 72];    // A tile fp16, pitch 72
    __shared__ __half sW0t[64 * 72];   // W0^T: [n][k]
    __shared__ __half sW1t[64 * 72];   // W1^T: [n][k]

    const int tid = threadIdx.x;
    const int warp = tid >> 5, lane = tid & 31;
    const int g = lane >> 2, tg = lane & 3;
    const int r0blk = blockIdx.x * 128;

    for (int idx = tid; idx < 4096; idx += 256) {
        const int k = idx >> 6, n = idx & 63;
        sW0t[n * 72 + k] = __float2half_rn(W0[idx]);
        sW1t[n * 72 + k] = __float2half_rn(W1[idx]);
    }
    {
        const int row = tid >> 1;
        const int c0 = (tid & 1) * 32;
        const int r = r0blk + row;
        if (r < NN) {
            const float4* src = (const float4*)(x + r * 64 + c0);
            #pragma unroll
            for (int i = 0; i < 8; i++) {
                const float4 v = src[i];
                *(__half2*)(sA + row * 72 + c0 + i * 4)     = __floats2half2_rn(v.x, v.y);
                *(__half2*)(sA + row * 72 + c0 + i * 4 + 2) = __floats2half2_rn(v.z, v.w);
            }
        } else {
            const __half2 z = __half2half2(__float2half(0.f));
            #pragma unroll
            for (int i = 0; i < 16; i++)
                *(__half2*)(sA + row * 72 + c0 + i * 2) = z;
        }
    }
    __syncthreads();

    const int rw = warp * 16;
    const int rA = r0blk + rw + g;
    const int rB = rA + 8;

    float acc[8][4];
    #pragma unroll
    for (int i = 0; i < 8; i++)
        #pragma unroll
        for (int j = 0; j < 4; j++) acc[i][j] = 0.f;

    // ---- MMA 1: x @ W0 ----
    #pragma unroll
    for (int k0 = 0; k0 < 64; k0 += 16) {
        const unsigned a0 = *(const unsigned*)(sA + (rw + g)     * 72 + k0 + 2 * tg);
        const unsigned a1 = *(const unsigned*)(sA + (rw + g + 8) * 72 + k0 + 2 * tg);
        const unsigned a2 = *(const unsigned*)(sA + (rw + g)     * 72 + k0 + 8 + 2 * tg);
        const unsigned a3 = *(const unsigned*)(sA + (rw + g + 8) * 72 + k0 + 8 + 2 * tg);
        #pragma unroll
        for (int i = 0; i < 8; i++)
            mma16n8k16(acc[i],
                       a0, a1, a2, a3,
                       *(const unsigned*)(sW0t + (i * 8 + g) * 72 + k0 + 2 * tg),
                       *(const unsigned*)(sW0t + (i * 8 + g) * 72 + k0 + 8 + 2 * tg));
    }

    // ---- epilogue 1: bias + relu; write fp32 out; store fp16 back to sA (own rows) ----
    #pragma unroll
    for (int i = 0; i < 8; i++) {
        const int c = i * 8 + 2 * tg;
        const float bx = b0[c], by = b0[c + 1];
        float v0 = fmaxf(acc[i][0] + bx, 0.f), v1 = fmaxf(acc[i][1] + by, 0.f);
        float v2 = fmaxf(acc[i][2] + bx, 0.f), v3 = fmaxf(acc[i][3] + by, 0.f);
        if (rA < NN) { float2 p = make_float2(v0, v1); *(float2*)(out + rA * 64 + c) = p; }
        if (rB < NN) { float2 p = make_float2(v2, v3); *(float2*)(out + rB * 64 + c) = p; }
        *(__half2*)(sA + (rw + g)     * 72 + c) = __floats2half2_rn(v0, v1);
        *(__half2*)(sA + (rw + g + 8) * 72 + c) = __floats2half2_rn(v2, v3);
    }
    __syncwarp();   // warp-local: MMA2's A fragments come from this warp's 16 rows only

    #pragma unroll
    for (int i = 0; i < 8; i++)
        #pragma unroll
        for (int j = 0; j < 4; j++) acc[i][j] = 0.f;

    // ---- MMA 2: relu(xW0+b0) @ W1 ----
    #pragma unroll
    for (int k0 = 0; k0 < 64; k0 += 16) {
        const unsigned a0 = *(const unsigned*)(sA + (rw + g)     * 72 + k0 + 2 * tg);
        const unsigned a1 = *(const unsigned*)(sA + (rw + g + 8) * 72 + k0 + 2 * tg);
        const unsigned a2 = *(const unsigned*)(sA + (rw + g)     * 72 + k0 + 8 + 2 * tg);
        const unsigned a3 = *(const unsigned*)(sA + (rw + g + 8) * 72 + k0 + 8 + 2 * tg);
        #pragma unroll
        for (int i = 0; i < 8; i++)
            mma16n8k16(acc[i],
                       a0, a1, a2, a3,
                       *(const unsigned*)(sW1t + (i * 8 + g) * 72 + k0 + 2 * tg),
                       *(const unsigned*)(sW1t + (i * 8 + g) * 72 + k0 + 8 + 2 * tg));
    }

    // ---- epilogue 2: fp16 hx + attention dots ----
    float vsA = 0.f, vdA = 0.f, vsB = 0.f, vdB = 0.f;
    #pragma unroll
    for (int i = 0; i < 8; i++) {
        const int c = i * 8 + 2 * tg;
        const float v0 = acc[i][0], v1 = acc[i][1], v2 = acc[i][2], v3 = acc[i][3];
        if (rA < NN) *(__half2*)(g_hxh + rA * 64 + c) = __floats2half2_rn(v0, v1);
        if (rB < NN) *(__half2*)(g_hxh + rB * 64 + c) = __floats2half2_rn(v2, v3);
        const float as0 = a_s[c], as1 = a_s[c + 1];
        const float ad0 = a_d[c], ad1 = a_d[c + 1];
        vsA += v0 * as0 + v1 * as1; vdA += v0 * ad0 + v1 * ad1;
        vsB += v2 * as0 + v3 * as1; vdB += v2 * ad0 + v3 * ad1;
    }
    #pragma unroll
    for (int o = 2; o > 0; o >>= 1) {
        vsA += __shfl_down_sync(0xffffffffu, vsA, o, 4);
        vdA += __shfl_down_sync(0xffffffffu, vdA, o, 4);
        vsB += __shfl_down_sync(0xffffffffu, vsB, o, 4);
        vdB += __shfl_down_sync(0xffffffffu, vdB, o, 4);
    }
    if (tg == 0) {
        if (rA < NN) { g_ssrc[rA] = vsA; g_sdst[rA] = vdA; }
        if (rB < NN) { g_ssrc[rB] = vsB; g_sdst[rB] = vdB; }
    }
}

// ---------------- single tensor-core GEMM (layer 2) ----------------
__global__ void __launch_bounds__(256) k_gemm_tc(
        const float* __restrict__ h, const float* __restrict__ W,
        const float* __restrict__ a_s, const float* __restrict__ a_d) {
    __shared__ __half sA[128 * 72];
    __shared__ __half sWt[64 * 72];

    const int tid = threadIdx.x;
    const int warp = tid >> 5, lane = tid & 31;
    const int g = lane >> 2, tg = lane & 3;
    const int r0blk = blockIdx.x * 128;

    for (int idx = tid; idx < 4096; idx += 256) {
        const int k = idx >> 6, n = idx & 63;
        sWt[n * 72 + k] = __float2half_rn(W[idx]);
    }
    {
        const int row = tid >> 1;
        const int c0 = (tid & 1) * 32;
        const int r = r0blk + row;
        if (r < NN) {
            const float4* src = (const float4*)(h + r * 64 + c0);
            #pragma unroll
            for (int i = 0; i < 8; i++) {
                const float4 v = src[i];
                *(__half2*)(sA + row * 72 + c0 + i * 4)     = __floats2half2_rn(v.x, v.y);
                *(__half2*)(sA + row * 72 + c0 + i * 4 + 2) = __floats2half2_rn(v.z, v.w);
            }
        } else {
            const __half2 z = __half2half2(__float2half(0.f));
            #pragma unroll
            for (int i = 0; i < 16; i++)
                *(__half2*)(sA + row * 72 + c0 + i * 2) = z;
        }
    }
    __syncthreads();

    const int rw = warp * 16;
    const int rA = r0blk + rw + g;
    const int rB = rA + 8;

    float acc[8][4];
    #pragma unroll
    for (int i = 0; i < 8; i++)
        #pragma unroll
        for (int j = 0; j < 4; j++) acc[i][j] = 0.f;

    #pragma unroll
    for (int k0 = 0; k0 < 64; k0 += 16) {
        const unsigned a0 = *(const unsigned*)(sA + (rw + g)     * 72 + k0 + 2 * tg);
        const unsigned a1 = *(const unsigned*)(sA + (rw + g + 8) * 72 + k0 + 2 * tg);
        const unsigned a2 = *(const unsigned*)(sA + (rw + g)     * 72 + k0 + 8 + 2 * tg);
        const unsigned a3 = *(const unsigned*)(sA + (rw + g + 8) * 72 + k0 + 8 + 2 * tg);
        #pragma unroll
        for (int i = 0; i < 8; i++)
            mma16n8k16(acc[i],
                       a0, a1, a2, a3,
                       *(const unsigned*)(sWt + (i * 8 + g) * 72 + k0 + 2 * tg),
                       *(const unsigned*)(sWt + (i * 8 + g) * 72 + k0 + 8 + 2 * tg));
    }

    float vsA = 0.f, vdA = 0.f, vsB = 0.f, vdB = 0.f;
    #pragma unroll
    for (int i = 0; i < 8; i++) {
        const int c = i * 8 + 2 * tg;
        const float v0 = acc[i][0], v1 = acc[i][1], v2 = acc[i][2], v3 = acc[i][3];
        if (rA < NN) *(__half2*)(g_hxh + rA * 64 + c) = __floats2half2_rn(v0, v1);
        if (rB < NN) *(__half2*)(g_hxh + rB * 64 + c) = __floats2half2_rn(v2, v3);
        const float as0 = a_s[c], as1 = a_s[c + 1];
        const float ad0 = a_d[c], ad1 = a_d[c + 1];
        vsA += v0 * as0 + v1 * as1; vdA += v0 * ad0 + v1 * ad1;
        vsB += v2 * as0 + v3 * as1; vdB += v2 * ad0 + v3 * ad1;
    }
    #pragma unroll
    for (int o = 2; o > 0; o >>= 1) {
        vsA += __shfl_down_sync(0xffffffffu, vsA, o, 4);
        vdA += __shfl_down_sync(0xffffffffu, vdA, o, 4);
        vsB += __shfl_down_sync(0xffffffffu, vsB, o, 4);
        vdB += __shfl_down_sync(0xffffffffu, vdB, o, 4);
    }
    if (tg == 0) {
        if (rA < NN) { g_ssrc[rA] = vsA; g_sdst[rA] = vdA; }
        if (rB < NN) { g_ssrc[rB] = vsB; g_sdst[rB] = vdB; }
    }
}

// ---------------- fused GAT aggregate: one warp per dst node ----------------
__global__ void __launch_bounds__(256) k_gat(float* __restrict__ out,
                                             const float* __restrict__ bias) {
    const int warp = threadIdx.x >> 5;
    const int lane = threadIdx.x & 31;
    const int node = blockIdx.x * 8 + warp;
    if (node >= NN) return;

    const int base = g_rowptr[node];
    const int end  = g_rowptr[node + 1];
    const float sdi = g_sdst[node];

    const int quarter = lane >> 3;
    const int sub     = lane & 7;
    float f[8];
    #pragma unroll
    for (int i = 0; i < 8; i++) f[i] = 0.f;
    float esum = 0.f;

    #pragma unroll 2
    for (int j = base + quarter; j < end; j += 4) {
        const int s = g_csr_src[j];
        float a = g_ssrc[s] + sdi;
        a = (a >= 0.f) ? a : 0.2f * a;
        const float e = __expf(a);
        const uint4 raw = *(const uint4*)(g_hxh + s * 64 + sub * 8);
        const __half2* hp = (const __half2*)&raw;
        const float2 f0 = __half22float2(hp[0]);
        const float2 f1 = __half22float2(hp[1]);
        const float2 f2 = __half22float2(hp[2]);
        const float2 f3 = __half22float2(hp[3]);
        f[0] = fmaf(e, f0.x, f[0]); f[1] = fmaf(e, f0.y, f[1]);
        f[2] = fmaf(e, f1.x, f[2]); f[3] = fmaf(e, f1.y, f[3]);
        f[4] = fmaf(e, f2.x, f[4]); f[5] = fmaf(e, f2.y, f[5]);
        f[6] = fmaf(e, f3.x, f[6]); f[7] = fmaf(e, f3.y, f[7]);
        esum += e;
    }
    #pragma unroll
    for (int o = 8; o <= 16; o <<= 1) {
        esum += __shfl_xor_sync(0xffffffffu, esum, o);
        #pragma unroll
        for (int i = 0; i < 8; i++)
            f[i] += __shfl_xor_sync(0xffffffffu, f[i], o);
    }

    const float inv = (end > base) ? (1.0f / esum) : 0.0f;

    if (quarter == 0) {
        float4 ob0 = *(float4*)(out + node * 64 + sub * 8);
        float4 ob1 = *(float4*)(out + node * 64 + sub * 8 + 4);
        const float4 bb0 = *(const float4*)(bias + sub * 8);
        const float4 bb1 = *(const float4*)(bias + sub * 8 + 4);
        ob0.x += fmaxf(fmaf(f[0], inv, bb0.x), 0.f);
        ob0.y += fmaxf(fmaf(f[1], inv, bb0.y), 0.f);
        ob0.z += fmaxf(fmaf(f[2], inv, bb0.z), 0.f);
        ob0.w += fmaxf(fmaf(f[3], inv, bb0.w), 0.f);
        ob1.x += fmaxf(fmaf(f[4], inv, bb1.x), 0.f);
        ob1.y += fmaxf(fmaf(f[5], inv, bb1.y), 0.f);
        ob1.z += fmaxf(fmaf(f[6], inv, bb1.z), 0.f);
        ob1.w += fmaxf(fmaf(f[7], inv, bb1.w), 0.f);
        *(float4*)(out + node * 64 + sub * 8)     = ob0;
        *(float4*)(out + node * 64 + sub * 8 + 4) = ob1;
    }
}

// ---------------- launch ----------------
extern "C" void kernel_launch(void* const* d_in, const int* in_sizes, int n_in,
                              void* d_out, int out_size) {
    const float* x   = (const float*)d_in[0];
    const int*   ei  = (const int*)d_in[1];
    const float* W0  = (const float*)d_in[4];
    const float* b0  = (const float*)d_in[5];
    const float* W1  = (const float*)d_in[6];
    const float* as1 = (const float*)d_in[7];
    const float* ad1 = (const float*)d_in[8];
    const float* b1  = (const float*)d_in[9];
    const float* W2  = (const float*)d_in[10];
    const float* as2 = (const float*)d_in[11];
    const float* ad2 = (const float*)d_in[12];
    const float* b2  = (const float*)d_in[13];
    float* out = (float*)d_out;

    const int edge4Blocks = (EE / 4 + 255) / 256;
    const int gemmBlocks  = (NN + 127) / 128;
    const int gatBlocks   = (NN + 7) / 8;

    k_hist<<<edge4Blocks, 256>>>(ei);
    k_scansum<<<SCAN_BLOCKS, 256>>>();
    k_scanout<<<SCAN_BLOCKS, 256>>>();
    k_fill<<<edge4Blocks, 256>>>(ei);

    // layers 0+1 GEMMs fused
    k_gemm2x<<<gemmBlocks, 256>>>(x, W0, b0, W1, as1, ad1, out);
    k_gat<<<gatBlocks, 256>>>(out, b1);

    // GAT layer 2
    k_gemm_tc<<<gemmBlocks, 256>>>(out, W2, as2, ad2);
    k_gat<<<gatBlocks, 256>>>(out, b2);
}